// round 12
// baseline (speedup 1.0000x reference)
#include <cuda_runtime.h>
#include <cstdint>

// Problem constants
#define MAX_DIST 35.0f
#define BOX 71            // ceil(2*35/1 + 1)
#define FDIM 32
#define BATCH 8
#define NPTS 16384

#define NPOINTS (BATCH * NPTS)               // 131,072
#define NCELLS  (BOX * BOX * BOX)            // 357,911
#define SLICE0_F4 (NCELLS * (FDIM / 4))      // 2,863,288 float4 = slice 0
#define TOTAL_F4  (SLICE0_F4 * BATCH)        // 22,906,304

// Per-cell linked lists. SENTINEL = 0; entries store pid+1.
// CUDA zero-initializes __device__ globals -> heads are valid-empty on the
// first call with NO init kernel. K2 resets each cell's head to 0 after
// consuming it, restoring the all-zero invariant for the next graph replay.
__device__ int d_head[NCELLS];               // 1.4 MB (zero-init = all empty)
__device__ int d_next[NPOINTS];              // 0.5 MB

// ---------------------------------------------------------------------------
// K1: build per-cell lists. cell = round-half-to-even(c+35) per axis
// (faithful to jnp.round); out-of-box points excluded (they contribute
// exactly +0.0 in the reference). All B*N points map into batch slice 0
// (reference's tf.zeros batch column). Stores pid+1 (0 = end-of-list).
// ---------------------------------------------------------------------------
__global__ void __launch_bounds__(256)
build_lists_kernel(const float* __restrict__ coords) {
    int i = blockIdx.x * blockDim.x + threadIdx.x;    // 0 .. NPOINTS-1
    float c0 = __ldg(&coords[i * 3 + 0]);
    float c1 = __ldg(&coords[i * 3 + 1]);
    float c2 = __ldg(&coords[i * 3 + 2]);
    int g0 = __float2int_rn(c0 + MAX_DIST);
    int g1 = __float2int_rn(c1 + MAX_DIST);
    int g2 = __float2int_rn(c2 + MAX_DIST);

    if ((unsigned)g0 < BOX && (unsigned)g1 < BOX && (unsigned)g2 < BOX) {
        int cell = (g0 * BOX + g1) * BOX + g2;
        d_next[i] = atomicExch(&d_head[cell], i + 1);
    }
}

// ---------------------------------------------------------------------------
// K2: gather + zero (PDL early-launch over K1). One thread per (cell, quad).
//   1. stream 7 zeros into slices 1..7 (independent of K1 -> runs while K1
//      is still executing),
//   2. cudaGridDependencySynchronize() -- wait for K1's lists,
//   3. walk the cell's list, accumulating feats[pid*8+q] (8 quad-threads of
//      a cell are consecutive in one warp -> 128B-coalesced feature reads,
//      head/next are L2-resident broadcasts),
//   4. q==0 thread resets the cell's head to 0 (restores invariant),
//   5. stream the accumulated float4 as the slice-0 value.
// Every output byte is written exactly once; no atomics on the output.
// ---------------------------------------------------------------------------
__global__ void __launch_bounds__(256)
gather_zero_kernel(const float4* __restrict__ feats,
                   float* __restrict__ out) {
    const int tid = blockIdx.x * blockDim.x + threadIdx.x;
    if (tid >= SLICE0_F4) return;                  // 72 pad threads

    float4* out4 = (float4*)out;
    const float4 z = make_float4(0.f, 0.f, 0.f, 0.f);

    // Zero slices 1..7 (each a fully coalesced stream per slice).
    #pragma unroll
    for (int k = 1; k < BATCH; k++) {
        __stcs(&out4[(long long)k * SLICE0_F4 + tid], z);
    }

    cudaGridDependencySynchronize();               // wait for K1's lists

    const int cell = tid >> 3;
    const int q = tid & 7;

    int e = d_head[cell];                          // all 8 quads read same
    if (q == 0 && e != 0) d_head[cell] = 0;        // restore invariant
    float4 acc = z;
    while (e != 0) {
        int pid = e - 1;
        float4 v = __ldg(&feats[(long long)pid * 8 + q]);
        acc.x += v.x; acc.y += v.y; acc.z += v.z; acc.w += v.w;
        e = d_next[pid];
    }
    __stcs(&out4[tid], acc);                       // slice 0, written once
}

extern "C" void kernel_launch(void* const* d_in, const int* in_sizes, int n_in,
                              void* d_out, int out_size) {
    const float* coords = (const float*)d_in[0];     // [8,16384,3] f32
    const float4* feats = (const float4*)d_in[1];    // [8,16384,32] f32 as float4
    float* out = (float*)d_out;                      // [8,71,71,71,32] f32

    // K1: build lists (first kernel, plain launch).
    build_lists_kernel<<<NPOINTS / 256, 256>>>(coords);

    // K2: gather + zero — PDL early launch (zero stream overlaps K1).
    cudaLaunchConfig_t cfg = {};
    cfg.gridDim = dim3((SLICE0_F4 + 255) / 256, 1, 1);  // 11185 blocks
    cfg.blockDim = dim3(256, 1, 1);
    cudaLaunchAttribute pdl[1];
    pdl[0].id = cudaLaunchAttributeProgrammaticStreamSerialization;
    pdl[0].val.programmaticStreamSerializationAllowed = 1;
    cfg.attrs = pdl; cfg.numAttrs = 1;
    cudaLaunchKernelEx(&cfg, gather_zero_kernel, feats, out);
}